// round 3
// baseline (speedup 1.0000x reference)
#include <cuda_runtime.h>
#include <cuda_bf16.h>

#define N_GRID 64
#define N1     65
#define B_PTS  262144
#define W_FEAT 256

// Streaming store helpers (evict-first: keep L2 for the gather table)
__device__ __forceinline__ void st_cs_f4(float4* p, float4 v) {
    asm volatile("st.global.cs.v4.f32 [%0], {%1,%2,%3,%4};"
                 :: "l"(p), "f"(v.x), "f"(v.y), "f"(v.z), "f"(v.w) : "memory");
}
__device__ __forceinline__ void st_cs_f(float* p, float v) {
    asm volatile("st.global.cs.f32 [%0], %1;" :: "l"(p), "f"(v) : "memory");
}

__global__ void __launch_bounds__(256)
trilerp_warp_kernel(const float* __restrict__ x,
                    const float* __restrict__ gval,
                    const float4* __restrict__ gfeat,
                    float* __restrict__ out_val,
                    float4* __restrict__ out_feat)
{
    const int gwarp = (blockIdx.x * blockDim.x + threadIdx.x) >> 5;
    const int lane  = threadIdx.x & 31;
    if (gwarp >= B_PTS) return;

    // Point coords (same addresses across warp -> L1 broadcast)
    const float x0 = __ldg(x + gwarp * 3 + 0);
    const float x1 = __ldg(x + gwarp * 3 + 1);
    const float x2 = __ldg(x + gwarp * 3 + 2);

    // rel = (x - (-1)) * (64/2)
    const float scale = (float)N_GRID / 2.0f;
    const float r0 = (x0 + 1.0f) * scale;
    const float r1 = (x1 + 1.0f) * scale;
    const float r2 = (x2 + 1.0f) * scale;

    const bool valid =
        (r0 >= 0.0f) && (r0 <= (float)N_GRID) &&
        (r1 >= 0.0f) && (r1 <= (float)N_GRID) &&
        (r2 >= 0.0f) && (r2 <= (float)N_GRID);

    int i0 = min(max((int)floorf(r0), 0), N_GRID - 1);
    int i1 = min(max((int)floorf(r1), 0), N_GRID - 1);
    int i2 = min(max((int)floorf(r2), 0), N_GRID - 1);

    const float t0 = r0 - (float)i0;
    const float t1 = r1 - (float)i1;
    const float t2 = r2 - (float)i2;

    const float wx[2] = {1.0f - t0, t0};
    const float wy[2] = {1.0f - t1, t1};
    const float wz[2] = {1.0f - t2, t2};

    const int base = (i0 * N1 + i1) * N1 + i2;

    // Precompute per-corner flat index and weight
    int   flat[8];
    float w[8];
#pragma unroll
    for (int c = 0; c < 8; c++) {
        const int ox = (c >> 2) & 1, oy = (c >> 1) & 1, oz = c & 1;
        flat[c] = base + (ox * N1 + oy) * N1 + oz;
        w[c]    = wx[ox] * wy[oy] * wz[oz];
    }

    float4 acc0 = make_float4(0.f, 0.f, 0.f, 0.f);
    float4 acc1 = make_float4(0.f, 0.f, 0.f, 0.f);
    float  accv = 0.f;

    if (valid) {
        // Issue all 16 feature loads (+8 scalar) with full unroll -> high MLP
#pragma unroll
        for (int c = 0; c < 8; c++) {
            const float4* row = gfeat + (size_t)flat[c] * (W_FEAT / 4);
            const float4 a = __ldg(row + lane);        // channels [4*lane .. 4*lane+3]
            const float4 b = __ldg(row + 32 + lane);   // channels [128+4*lane ..]
            const float  ww = w[c];
            acc0.x = fmaf(ww, a.x, acc0.x);
            acc0.y = fmaf(ww, a.y, acc0.y);
            acc0.z = fmaf(ww, a.z, acc0.z);
            acc0.w = fmaf(ww, a.w, acc0.w);
            acc1.x = fmaf(ww, b.x, acc1.x);
            acc1.y = fmaf(ww, b.y, acc1.y);
            acc1.z = fmaf(ww, b.z, acc1.z);
            acc1.w = fmaf(ww, b.w, acc1.w);
            if (lane == 0) accv = fmaf(ww, __ldg(gval + flat[c]), accv);
        }
    }
    // invalid -> zeros (accs already zero)

    // Streaming stores: coalesced 512B per instruction across the warp
    float4* frow = out_feat + (size_t)gwarp * (W_FEAT / 4);
    st_cs_f4(frow + lane,      acc0);
    st_cs_f4(frow + 32 + lane, acc1);
    if (lane == 0) st_cs_f(out_val + gwarp, accv);
}

extern "C" void kernel_launch(void* const* d_in, const int* in_sizes, int n_in,
                              void* d_out, int out_size) {
    const float* x  = (const float*)d_in[0];   // (B, 3)
    const float* gv = (const float*)d_in[1];   // (65^3, 1)
    const float* gf = (const float*)d_in[2];   // (65^3, 256)

    float* out_val  = (float*)d_out;           // (B, 1)
    float* out_feat = out_val + B_PTS;         // (B, 256)

    // One warp per point: 256 threads = 8 points/block
    const int threads = 256;
    const int blocks  = B_PTS / (threads / 32);
    trilerp_warp_kernel<<<blocks, threads>>>(
        x, gv, (const float4*)gf, out_val, (float4*)out_feat);
}

// round 6
// speedup vs baseline: 1.7106x; 1.7106x over previous
#include <cuda_runtime.h>
#include <cuda_bf16.h>

#define N_GRID 64
#define N1     65
#define B_PTS  262144
#define W_FEAT 256
#define CELLS  (N_GRID * N_GRID * N_GRID)   // 262144

// ---------------- device scratch (no allocations allowed) ----------------
__device__ unsigned int g_hist[CELLS];      // histogram -> exclusive offsets (destroyed by scatter)
__device__ unsigned int g_bsums[256];       // block sums for scan
__device__ unsigned int g_cellid[B_PTS];    // cell id per point
__device__ unsigned int g_perm[B_PTS];      // sorted slot -> original point id
__device__ float4       g_sorted[B_PTS];    // sorted slot -> (t0,t1,t2, packed base|valid)

// Streaming store helpers (evict-first: keep L2 for the gather table)
__device__ __forceinline__ void st_cs_f4(float4* p, float4 v) {
    asm volatile("st.global.cs.v4.f32 [%0], {%1,%2,%3,%4};"
                 :: "l"(p), "f"(v.x), "f"(v.y), "f"(v.z), "f"(v.w) : "memory");
}
__device__ __forceinline__ void st_cs_f(float* p, float v) {
    asm volatile("st.global.cs.f32 [%0], %1;" :: "l"(p), "f"(v) : "memory");
}

// Shared point math
__device__ __forceinline__ void point_math(float x0, float x1, float x2,
                                           int& i0, int& i1, int& i2,
                                           float& t0, float& t1, float& t2,
                                           bool& valid) {
    const float scale = (float)N_GRID / 2.0f;
    const float r0 = (x0 + 1.0f) * scale;
    const float r1 = (x1 + 1.0f) * scale;
    const float r2 = (x2 + 1.0f) * scale;
    valid = (r0 >= 0.0f) && (r0 <= (float)N_GRID) &&
            (r1 >= 0.0f) && (r1 <= (float)N_GRID) &&
            (r2 >= 0.0f) && (r2 <= (float)N_GRID);
    i0 = min(max((int)floorf(r0), 0), N_GRID - 1);
    i1 = min(max((int)floorf(r1), 0), N_GRID - 1);
    i2 = min(max((int)floorf(r2), 0), N_GRID - 1);
    t0 = r0 - (float)i0;
    t1 = r1 - (float)i1;
    t2 = r2 - (float)i2;
}

// ---------------- pass 0: zero histogram ----------------
__global__ void zero_hist_kernel() {
    int i = blockIdx.x * blockDim.x + threadIdx.x;
    g_hist[i] = 0u;
}

// ---------------- pass 1: histogram + cell ids ----------------
__global__ void hist_kernel(const float* __restrict__ x) {
    int p = blockIdx.x * blockDim.x + threadIdx.x;
    if (p >= B_PTS) return;
    const float x0 = x[p * 3 + 0];
    const float x1 = x[p * 3 + 1];
    const float x2 = x[p * 3 + 2];
    int i0, i1, i2; float t0, t1, t2; bool valid;
    point_math(x0, x1, x2, i0, i1, i2, t0, t1, t2, valid);
    unsigned int cell = (unsigned)((i0 * N_GRID + i1) * N_GRID + i2);
    g_cellid[p] = cell;
    atomicAdd(&g_hist[cell], 1u);
}

// ---------------- pass 2: exclusive scan (3 kernels) ----------------
__global__ void scan_block_kernel() {           // 256 blocks x 1024 threads
    __shared__ unsigned int s[1024];
    const int tid = threadIdx.x;
    const int i   = blockIdx.x * 1024 + tid;
    unsigned int v = g_hist[i];
    s[tid] = v;
    __syncthreads();
    #pragma unroll
    for (int off = 1; off < 1024; off <<= 1) {
        unsigned int t = (tid >= off) ? s[tid - off] : 0u;
        __syncthreads();
        s[tid] += t;
        __syncthreads();
    }
    g_hist[i] = s[tid] - v;                     // exclusive
    if (tid == 1023) g_bsums[blockIdx.x] = s[1023];
}

__global__ void scan_sums_kernel() {            // 1 block x 256 threads
    __shared__ unsigned int s[256];
    const int tid = threadIdx.x;
    unsigned int v = g_bsums[tid];
    s[tid] = v;
    __syncthreads();
    #pragma unroll
    for (int off = 1; off < 256; off <<= 1) {
        unsigned int t = (tid >= off) ? s[tid - off] : 0u;
        __syncthreads();
        s[tid] += t;
        __syncthreads();
    }
    g_bsums[tid] = s[tid] - v;                  // exclusive
}

__global__ void add_sums_kernel() {             // 256 blocks x 1024 threads
    g_hist[blockIdx.x * 1024 + threadIdx.x] += g_bsums[blockIdx.x];
}

// ---------------- pass 3: scatter into sorted order ----------------
__global__ void scatter_kernel(const float* __restrict__ x) {
    int p = blockIdx.x * blockDim.x + threadIdx.x;
    if (p >= B_PTS) return;
    const float x0 = x[p * 3 + 0];
    const float x1 = x[p * 3 + 1];
    const float x2 = x[p * 3 + 2];
    int i0, i1, i2; float t0, t1, t2; bool valid;
    point_math(x0, x1, x2, i0, i1, i2, t0, t1, t2, valid);

    const unsigned int cell = g_cellid[p];
    const unsigned int slot = atomicAdd(&g_hist[cell], 1u);   // fetch-and-add on offsets

    const int base   = (i0 * N1 + i1) * N1 + i2;              // < 2^19
    const int packed = base | (valid ? (1 << 23) : 0);

    g_perm[slot]   = (unsigned)p;
    g_sorted[slot] = make_float4(t0, t1, t2, __int_as_float(packed));
}

// ---------------- pass 4: main gather (1 warp / point, sorted order) ----------------
__global__ void __launch_bounds__(256)
trilerp_sorted_kernel(const float* __restrict__ gval,
                      const float4* __restrict__ gfeat,
                      float* __restrict__ out_val,
                      float4* __restrict__ out_feat)
{
    const int slot = (blockIdx.x * blockDim.x + threadIdx.x) >> 5;
    const int lane = threadIdx.x & 31;
    if (slot >= B_PTS) return;

    // warp-uniform metadata loads (broadcast)
    const float4 s   = __ldg(&g_sorted[slot]);
    const unsigned p = __ldg(&g_perm[slot]);
    const int packed = __float_as_int(s.w);
    const int base   = packed & 0x7FFFFF;
    const bool valid = (packed >> 23) & 1;

    const float wx[2] = {1.0f - s.x, s.x};
    const float wy[2] = {1.0f - s.y, s.y};
    const float wz[2] = {1.0f - s.z, s.z};

    int   flat[8];
    float w[8];
#pragma unroll
    for (int c = 0; c < 8; c++) {
        const int ox = (c >> 2) & 1, oy = (c >> 1) & 1, oz = c & 1;
        flat[c] = base + (ox * N1 + oy) * N1 + oz;
        w[c]    = wx[ox] * wy[oy] * wz[oz];
    }

    float4 acc0 = make_float4(0.f, 0.f, 0.f, 0.f);
    float4 acc1 = make_float4(0.f, 0.f, 0.f, 0.f);
    float  accv = 0.f;

    if (valid) {
#pragma unroll
        for (int c = 0; c < 8; c++) {
            const float4* row = gfeat + (size_t)flat[c] * (W_FEAT / 4);
            const float4 a = __ldg(row + lane);
            const float4 b = __ldg(row + 32 + lane);
            const float  ww = w[c];
            acc0.x = fmaf(ww, a.x, acc0.x);
            acc0.y = fmaf(ww, a.y, acc0.y);
            acc0.z = fmaf(ww, a.z, acc0.z);
            acc0.w = fmaf(ww, a.w, acc0.w);
            acc1.x = fmaf(ww, b.x, acc1.x);
            acc1.y = fmaf(ww, b.y, acc1.y);
            acc1.z = fmaf(ww, b.z, acc1.z);
            acc1.w = fmaf(ww, b.w, acc1.w);
            if (lane == 0) accv = fmaf(ww, __ldg(gval + flat[c]), accv);
        }
    }

    // streaming stores to the ORIGINAL point's row (full-row coalesced)
    float4* frow = out_feat + (size_t)p * (W_FEAT / 4);
    st_cs_f4(frow + lane,      acc0);
    st_cs_f4(frow + 32 + lane, acc1);
    if (lane == 0) st_cs_f(out_val + p, accv);
}

// ---------------- launch ----------------
extern "C" void kernel_launch(void* const* d_in, const int* in_sizes, int n_in,
                              void* d_out, int out_size) {
    const float* x  = (const float*)d_in[0];   // (B, 3)
    const float* gv = (const float*)d_in[1];   // (65^3, 1)
    const float* gf = (const float*)d_in[2];   // (65^3, 256)

    float* out_val  = (float*)d_out;           // (B, 1)
    float* out_feat = out_val + B_PTS;         // (B, 256)

    // 0: zero histogram (262144 = 1024 blocks x 256)
    zero_hist_kernel<<<CELLS / 256, 256>>>();
    // 1: histogram + cell ids
    hist_kernel<<<B_PTS / 256, 256>>>(x);
    // 2: exclusive scan of 262144 counters
    scan_block_kernel<<<CELLS / 1024, 1024>>>();
    scan_sums_kernel<<<1, 256>>>();
    add_sums_kernel<<<CELLS / 1024, 1024>>>();
    // 3: scatter into sorted order
    scatter_kernel<<<B_PTS / 256, 256>>>(x);
    // 4: main gather, sorted order, 1 warp per point
    trilerp_sorted_kernel<<<B_PTS / 8, 256>>>(
        gv, (const float4*)gf, out_val, (float4*)out_feat);
}